// round 3
// baseline (speedup 1.0000x reference)
#include <cuda_runtime.h>
#include <math.h>

#define N_SEQ   2048
#define SEQ_LEN 24
#define SEQ_C   9
#define N_FILT  32
#define KM      16
#define HID     128
#define NCLS    10

// One fused kernel: per-block kernel transpose -> 4 warp-parallel DTWs -> block MLP.
__global__ __launch_bounds__(128) void fused_dtwnet(
    const float* __restrict__ x, const float* __restrict__ kernels,
    const float* __restrict__ W1, const float* __restrict__ b1,
    const float* __restrict__ W2, const float* __restrict__ b2,
    const float* __restrict__ Wl, const float* __restrict__ bl,
    float* __restrict__ out) {

    __shared__ float kT[KM * SEQ_C * N_FILT];   // [i][c][f]  (18KB)
    __shared__ float knS[KM * N_FILT];          // [i][f]
    __shared__ float seqS[4][SEQ_LEN * SEQ_C];
    __shared__ float snormS[4][SEQ_LEN];
    __shared__ float fS[4][N_FILT];
    __shared__ float t1S[4][HID];
    __shared__ float t2S[4][HID];

    const int t    = threadIdx.x;
    const int wid  = t >> 5;
    const int lane = t & 31;
    const int s0   = blockIdx.x * 4;

    // ---- Prologue: transpose kernels into shared (coalesced global reads) ----
    for (int idx = t; idx < KM * SEQ_C * N_FILT; idx += 128) {
        int f   = idx / (KM * SEQ_C);
        int rem = idx - f * (KM * SEQ_C);       // i*9 + c
        kT[rem * N_FILT + f] = kernels[idx];
    }

    // ---- Per-warp: stage sequence ----
    {
        const float* xs = x + (s0 + wid) * (SEQ_LEN * SEQ_C);
        for (int i = lane; i < SEQ_LEN * SEQ_C; i += 32) seqS[wid][i] = xs[i];
    }
    __syncthreads();

    // ---- knorm from shared kT; snorm per warp ----
    for (int idx = t; idx < KM * N_FILT; idx += 128) {
        int i = idx >> 5;
        int f = idx & 31;
        float a = 0.f;
#pragma unroll
        for (int c = 0; c < SEQ_C; ++c) {
            float v = kT[(i * SEQ_C + c) * N_FILT + f];
            a = fmaf(v, v, a);
        }
        knS[idx] = a;
    }
    if (lane < SEQ_LEN) {
        float a = 0.f;
#pragma unroll
        for (int c = 0; c < SEQ_C; ++c) {
            float v = seqS[wid][lane * SEQ_C + c];
            a = fmaf(v, v, a);
        }
        snormS[wid][lane] = a;
    }
    __syncthreads();

    // ---- DTW: lane = filter, rolling row in registers ----
    const int f = lane;
    float Dp[SEQ_LEN];

    // Row 0: cumsum of C[0][j]
    {
        float k0[SEQ_C];
#pragma unroll
        for (int c = 0; c < SEQ_C; ++c) k0[c] = kT[c * N_FILT + f];
        float kn = knS[f];
        float run = 0.f;
#pragma unroll
        for (int j = 0; j < SEQ_LEN; ++j) {
            float dot = 0.f;
#pragma unroll
            for (int c = 0; c < SEQ_C; ++c) dot = fmaf(k0[c], seqS[wid][j * SEQ_C + c], dot);
            float Cv = fmaf(-2.f, dot, kn + snormS[wid][j]);
            run = (j == 0) ? Cv : (run + Cv);
            Dp[j] = run;
        }
    }

    const float INF = __int_as_float(0x7f800000);

    // Rows 1..15 in 3 sweeps of 5
    for (int sw = 0; sw < 3; ++sw) {
        const int i0 = 1 + sw * 5;
        float kr[5][SEQ_C], knr[5], left[5];
#pragma unroll
        for (int r = 0; r < 5; ++r) {
#pragma unroll
            for (int c = 0; c < SEQ_C; ++c)
                kr[r][c] = kT[((i0 + r) * SEQ_C + c) * N_FILT + f];
            knr[r] = knS[(i0 + r) * N_FILT + f];
            left[r] = INF;
        }
        float diagc = INF;
#pragma unroll
        for (int j = 0; j < SEQ_LEN; ++j) {
            float sv[SEQ_C];
#pragma unroll
            for (int c = 0; c < SEQ_C; ++c) sv[c] = seqS[wid][j * SEQ_C + c];
            float sn = snormS[wid][j];
            float up = Dp[j];
            float oldup = up;
            float diag = diagc;
#pragma unroll
            for (int r = 0; r < 5; ++r) {
                float dot = 0.f;
#pragma unroll
                for (int c = 0; c < SEQ_C; ++c) dot = fmaf(kr[r][c], sv[c], dot);
                float Cv = fmaf(-2.f, dot, knr[r] + sn);
                float best = fminf(left[r], fminf(up, diag));
                float d = Cv + best;
                diag = left[r];
                left[r] = d;
                up = d;
            }
            Dp[j] = up;
            diagc = oldup;
        }
    }

    fS[wid][f] = Dp[SEQ_LEN - 1];
    __syncthreads();

    // ---- MLP head: thread t = hidden unit, 4 sequences per block ----
    float a0 = b1[t], a1 = a0, a2 = a0, a3 = a0;
#pragma unroll
    for (int ff = 0; ff < N_FILT; ++ff) {
        float w = W1[ff * HID + t];
        a0 = fmaf(fS[0][ff], w, a0);
        a1 = fmaf(fS[1][ff], w, a1);
        a2 = fmaf(fS[2][ff], w, a2);
        a3 = fmaf(fS[3][ff], w, a3);
    }
    t1S[0][t] = fmaxf(a0, 0.f);
    t1S[1][t] = fmaxf(a1, 0.f);
    t1S[2][t] = fmaxf(a2, 0.f);
    t1S[3][t] = fmaxf(a3, 0.f);
    __syncthreads();

    float c0 = b2[t], c1 = c0, c2 = c0, c3 = c0;
#pragma unroll 8
    for (int h = 0; h < HID; ++h) {
        float w = W2[h * HID + t];
        c0 = fmaf(t1S[0][h], w, c0);
        c1 = fmaf(t1S[1][h], w, c1);
        c2 = fmaf(t1S[2][h], w, c2);
        c3 = fmaf(t1S[3][h], w, c3);
    }
    t2S[0][t] = fmaxf(c0, 0.f);
    t2S[1][t] = fmaxf(c1, 0.f);
    t2S[2][t] = fmaxf(c2, 0.f);
    t2S[3][t] = fmaxf(c3, 0.f);
    __syncthreads();

    // Logits + softmax: warp w -> sequence s0 + w
    float acc[NCLS];
#pragma unroll
    for (int c = 0; c < NCLS; ++c) acc[c] = 0.f;
#pragma unroll
    for (int hh = 0; hh < 4; ++hh) {
        int h = lane + hh * 32;
        float v = t2S[wid][h];
#pragma unroll
        for (int c = 0; c < NCLS; ++c) acc[c] = fmaf(v, Wl[h * NCLS + c], acc[c]);
    }
#pragma unroll
    for (int off = 16; off > 0; off >>= 1) {
#pragma unroll
        for (int c = 0; c < NCLS; ++c)
            acc[c] += __shfl_xor_sync(0xffffffffu, acc[c], off);
    }
    if (lane == 0) {
        float mx = -INF;
#pragma unroll
        for (int c = 0; c < NCLS; ++c) {
            acc[c] += bl[c];
            mx = fmaxf(mx, acc[c]);
        }
        float e[NCLS];
        float sum = 0.f;
#pragma unroll
        for (int c = 0; c < NCLS; ++c) {
            e[c] = __expf(acc[c] - mx);
            sum += e[c];
        }
        float inv = 1.f / sum;
#pragma unroll
        for (int c = 0; c < NCLS; ++c)
            out[(s0 + wid) * NCLS + c] = e[c] * inv;
    }
}

extern "C" void kernel_launch(void* const* d_in, const int* in_sizes, int n_in,
                              void* d_out, int out_size) {
    const float* x       = (const float*)d_in[0];
    const float* kernels = (const float*)d_in[1];
    const float* W1      = (const float*)d_in[2];
    const float* b1      = (const float*)d_in[3];
    const float* W2      = (const float*)d_in[4];
    const float* b2      = (const float*)d_in[5];
    const float* Wl      = (const float*)d_in[6];
    const float* bl      = (const float*)d_in[7];
    float* out = (float*)d_out;

    fused_dtwnet<<<N_SEQ / 4, 128>>>(x, kernels, W1, b1, W2, b2, Wl, bl, out);
}

// round 4
// speedup vs baseline: 1.4732x; 1.4732x over previous
#include <cuda_runtime.h>
#include <math.h>

#define N_SEQ   2048
#define SEQ_LEN 24
#define SEQ_C   9
#define N_FILT  32
#define KM      16
#define HID     128
#define NCLS    10

typedef unsigned long long ull;

__device__ float g_feats[N_SEQ * N_FILT];

__device__ __forceinline__ ull pack2(float lo, float hi) {
    ull r; asm("mov.b64 %0, {%1, %2};" : "=l"(r) : "f"(lo), "f"(hi)); return r;
}
__device__ __forceinline__ void fma2(ull& d, ull a, ull b) {
    asm("fma.rn.f32x2 %0, %1, %2, %3;" : "=l"(d) : "l"(a), "l"(b), "l"(d));
}
__device__ __forceinline__ void unpack2(ull v, float& lo, float& hi) {
    asm("mov.b64 {%0, %1}, %2;" : "=f"(lo), "=f"(hi) : "l"(v));
}

// ---------------------------------------------------------------------------
// DTW: 128 threads = 4 independent warps, warp = sequence, lane = filter.
// Forward DP only (D[m-1][n-1] == backtracked path-cost sum, exact identity,
// validated rel_err ~1e-25 in prior rounds). Rolling row in registers.
// Cost via C = |k|^2 + |s|^2 - 2<k,s> with f32x2-packed dot products and the
// norm terms folded into the packed accumulator init.
// ---------------------------------------------------------------------------
__global__ __launch_bounds__(128) void dtw_kernel(const float* __restrict__ x,
                                                  const float* __restrict__ kernels) {
    __shared__ float2 seq2S[4][SEQ_LEN][4];  // channel pairs (c0..c7)
    __shared__ float  s8S[4][SEQ_LEN];       // channel 8
    __shared__ float  hsnS[4][SEQ_LEN];      // -0.5*|s_j|^2

    const int wid = threadIdx.x >> 5;
    const int f   = threadIdx.x & 31;
    const int s   = blockIdx.x * 4 + wid;

    // Stage sequence, packed into float2 channel-pairs
    const float* xs = x + s * (SEQ_LEN * SEQ_C);
    for (int i = f; i < SEQ_LEN * SEQ_C; i += 32) {
        int j = i / SEQ_C, c = i - j * SEQ_C;
        float v = xs[i];
        if (c == 8) s8S[wid][j] = v;
        else ((float*)&seq2S[wid][j][c >> 1])[c & 1] = v;
    }
    __syncwarp();
    if (f < SEQ_LEN) {
        float a = 0.f;
#pragma unroll
        for (int p = 0; p < 4; ++p) {
            float2 q = seq2S[wid][f][p];
            a = fmaf(q.x, q.x, a);
            a = fmaf(q.y, q.y, a);
        }
        float v8 = s8S[wid][f];
        a = fmaf(v8, v8, a);
        hsnS[wid][f] = -0.5f * a;
    }
    __syncwarp();

    const float* kf = kernels + f * (KM * SEQ_C);  // this lane's filter
    float Dp[SEQ_LEN];

    // ---- Row 0: cumulative sum of C[0][j] ----
    {
        float kv[SEQ_C];
#pragma unroll
        for (int c = 0; c < SEQ_C; ++c) kv[c] = __ldg(kf + c);
        ull k2[4];
#pragma unroll
        for (int p = 0; p < 4; ++p) k2[p] = pack2(kv[2 * p], kv[2 * p + 1]);
        float kn = 0.f;
#pragma unroll
        for (int c = 0; c < SEQ_C; ++c) kn = fmaf(kv[c], kv[c], kn);
        float hkn = -0.5f * kn;

        float run = 0.f;
#pragma unroll
        for (int j = 0; j < SEQ_LEN; ++j) {
            ull acc = pack2(hkn, hsnS[wid][j]);
#pragma unroll
            for (int p = 0; p < 4; ++p)
                fma2(acc, k2[p], *reinterpret_cast<const ull*>(&seq2S[wid][j][p]));
            float lo, hi; unpack2(acc, lo, hi);
            float t = fmaf(kv[8], s8S[wid][j], lo + hi);
            run = fmaf(-2.f, t, run);   // run += kn + sn - 2*dot
            Dp[j] = run;
        }
    }

    const float INF = __int_as_float(0x7f800000);

    // ---- Rows 1..15 in 3 sweeps of 5 rows ----
    for (int sw = 0; sw < 3; ++sw) {
        const int i0 = 1 + sw * 5;
        ull  kr2[5][4];
        float kr8[5], hkn[5], left[5];
#pragma unroll
        for (int r = 0; r < 5; ++r) {
            float kv[SEQ_C];
#pragma unroll
            for (int c = 0; c < SEQ_C; ++c) kv[c] = __ldg(kf + (i0 + r) * SEQ_C + c);
#pragma unroll
            for (int p = 0; p < 4; ++p) kr2[r][p] = pack2(kv[2 * p], kv[2 * p + 1]);
            kr8[r] = kv[8];
            float kn = 0.f;
#pragma unroll
            for (int c = 0; c < SEQ_C; ++c) kn = fmaf(kv[c], kv[c], kn);
            hkn[r] = -0.5f * kn;
            left[r] = INF;
        }
        float diagc = INF;
#pragma unroll
        for (int j = 0; j < SEQ_LEN; ++j) {
            ull sv[4];
#pragma unroll
            for (int p = 0; p < 4; ++p)
                sv[p] = *reinterpret_cast<const ull*>(&seq2S[wid][j][p]);
            const float s8  = s8S[wid][j];
            const float hsn = hsnS[wid][j];

            float up = Dp[j];
            float oldup = up;
            float diag = diagc;
#pragma unroll
            for (int r = 0; r < 5; ++r) {
                ull acc = pack2(hkn[r], hsn);
                fma2(acc, kr2[r][0], sv[0]);
                fma2(acc, kr2[r][1], sv[1]);
                fma2(acc, kr2[r][2], sv[2]);
                fma2(acc, kr2[r][3], sv[3]);
                float lo, hi; unpack2(acc, lo, hi);
                float t = fmaf(kr8[r], s8, lo + hi);         // dot - (kn+sn)/2
                float best = fminf(left[r], fminf(up, diag));
                float d = fmaf(-2.f, t, best);               // C + best
                diag = left[r];
                left[r] = d;
                up = d;
            }
            Dp[j] = up;
            diagc = oldup;
        }
    }

    g_feats[s * N_FILT + f] = Dp[SEQ_LEN - 1];
}

// ---------------------------------------------------------------------------
// MLP head (unchanged from the 37.6us version): block = 128 threads, 4 seqs.
// ---------------------------------------------------------------------------
__global__ __launch_bounds__(128) void mlp_kernel(
    const float* __restrict__ W1, const float* __restrict__ b1,
    const float* __restrict__ W2, const float* __restrict__ b2,
    const float* __restrict__ Wl, const float* __restrict__ bl,
    float* __restrict__ out) {
    __shared__ float fS[4][N_FILT];
    __shared__ float t1S[4][HID];
    __shared__ float t2S[4][HID];

    const int t = threadIdx.x;
    const int s0 = blockIdx.x * 4;

    fS[t >> 5][t & 31] = g_feats[s0 * N_FILT + t];
    __syncthreads();

    float a0 = b1[t], a1 = a0, a2 = a0, a3 = a0;
#pragma unroll
    for (int ff = 0; ff < N_FILT; ++ff) {
        float w = W1[ff * HID + t];
        a0 = fmaf(fS[0][ff], w, a0);
        a1 = fmaf(fS[1][ff], w, a1);
        a2 = fmaf(fS[2][ff], w, a2);
        a3 = fmaf(fS[3][ff], w, a3);
    }
    t1S[0][t] = fmaxf(a0, 0.f);
    t1S[1][t] = fmaxf(a1, 0.f);
    t1S[2][t] = fmaxf(a2, 0.f);
    t1S[3][t] = fmaxf(a3, 0.f);
    __syncthreads();

    float c0 = b2[t], c1 = c0, c2 = c0, c3 = c0;
#pragma unroll 8
    for (int h = 0; h < HID; ++h) {
        float w = W2[h * HID + t];
        c0 = fmaf(t1S[0][h], w, c0);
        c1 = fmaf(t1S[1][h], w, c1);
        c2 = fmaf(t1S[2][h], w, c2);
        c3 = fmaf(t1S[3][h], w, c3);
    }
    t2S[0][t] = fmaxf(c0, 0.f);
    t2S[1][t] = fmaxf(c1, 0.f);
    t2S[2][t] = fmaxf(c2, 0.f);
    t2S[3][t] = fmaxf(c3, 0.f);
    __syncthreads();

    const int wid = t >> 5;
    const int lane = t & 31;
    float acc[NCLS];
#pragma unroll
    for (int c = 0; c < NCLS; ++c) acc[c] = 0.f;
#pragma unroll
    for (int hh = 0; hh < 4; ++hh) {
        int h = lane + hh * 32;
        float v = t2S[wid][h];
#pragma unroll
        for (int c = 0; c < NCLS; ++c) acc[c] = fmaf(v, Wl[h * NCLS + c], acc[c]);
    }
#pragma unroll
    for (int off = 16; off > 0; off >>= 1) {
#pragma unroll
        for (int c = 0; c < NCLS; ++c)
            acc[c] += __shfl_xor_sync(0xffffffffu, acc[c], off);
    }
    if (lane == 0) {
        float mx = -__int_as_float(0x7f800000);
#pragma unroll
        for (int c = 0; c < NCLS; ++c) {
            acc[c] += bl[c];
            mx = fmaxf(mx, acc[c]);
        }
        float e[NCLS];
        float sum = 0.f;
#pragma unroll
        for (int c = 0; c < NCLS; ++c) {
            e[c] = expf(acc[c] - mx);
            sum += e[c];
        }
        float inv = 1.f / sum;
#pragma unroll
        for (int c = 0; c < NCLS; ++c)
            out[(s0 + wid) * NCLS + c] = e[c] * inv;
    }
}

extern "C" void kernel_launch(void* const* d_in, const int* in_sizes, int n_in,
                              void* d_out, int out_size) {
    const float* x       = (const float*)d_in[0];
    const float* kernels = (const float*)d_in[1];
    const float* W1      = (const float*)d_in[2];
    const float* b1      = (const float*)d_in[3];
    const float* W2      = (const float*)d_in[4];
    const float* b2      = (const float*)d_in[5];
    const float* Wl      = (const float*)d_in[6];
    const float* bl      = (const float*)d_in[7];
    float* out = (float*)d_out;

    dtw_kernel<<<N_SEQ / 4, 128>>>(x, kernels);
    mlp_kernel<<<N_SEQ / 4, 128>>>(W1, b1, W2, b2, Wl, bl, out);
}

// round 5
// speedup vs baseline: 1.8336x; 1.2446x over previous
#include <cuda_runtime.h>
#include <math.h>

#define N_SEQ   2048
#define SEQ_LEN 24
#define SEQ_C   9
#define N_FILT  32
#define KM      16
#define HID     128
#define NCLS    10

#define KPAD 33                     // padded filter stride (conflict-free)
#define SEQS_PER_DTW_BLK 8
#define SEQS_PER_MLP_BLK 8

typedef unsigned long long ull;

__device__ float g_feats[N_SEQ * N_FILT];

__device__ __forceinline__ ull pack2(float lo, float hi) {
    ull r; asm("mov.b64 %0, {%1, %2};" : "=l"(r) : "f"(lo), "f"(hi)); return r;
}
__device__ __forceinline__ void fma2(ull& d, ull a, ull b) {
    asm("fma.rn.f32x2 %0, %1, %2, %3;" : "=l"(d) : "l"(a), "l"(b), "l"(d));
}
__device__ __forceinline__ void unpack2(ull v, float& lo, float& hi) {
    asm("mov.b64 {%0, %1}, %2;" : "=f"(lo), "=f"(hi) : "l"(v));
}

// ---------------------------------------------------------------------------
// DTW: 256 threads = 8 warps, warp = sequence, lane = filter.
// Kernel weights staged per-block into padded smem (coalesced loads,
// conflict-free stores & reads). Forward DP == backtracked path sum (exact).
// ---------------------------------------------------------------------------
__global__ __launch_bounds__(256) void dtw_kernel(const float* __restrict__ x,
                                                  const float* __restrict__ kernels) {
    __shared__ float  kTS[KM * SEQ_C * KPAD];          // [i*9+c][f], padded
    __shared__ float  knS[KM * N_FILT];                // -0.5*|k_i|^2, [i][f]
    __shared__ float2 seq2S[SEQS_PER_DTW_BLK][SEQ_LEN][4];
    __shared__ float  s8S[SEQS_PER_DTW_BLK][SEQ_LEN];
    __shared__ float  hsnS[SEQS_PER_DTW_BLK][SEQ_LEN]; // -0.5*|s_j|^2

    const int t   = threadIdx.x;
    const int wid = t >> 5;
    const int f   = t & 31;
    const int s   = blockIdx.x * SEQS_PER_DTW_BLK + wid;

    // Stage kernels: read kernels[f][i][c] coalesced, write transposed+padded.
    for (int idx = t; idx < N_FILT * KM * SEQ_C; idx += 256) {
        int fk  = idx / (KM * SEQ_C);
        int rem = idx - fk * (KM * SEQ_C);      // i*9 + c
        kTS[rem * KPAD + fk] = kernels[idx];
    }

    // Stage this warp's sequence into packed channel-pairs.
    {
        const float* xs = x + s * (SEQ_LEN * SEQ_C);
        for (int i = f; i < SEQ_LEN * SEQ_C; i += 32) {
            int j = i / SEQ_C, c = i - j * SEQ_C;
            float v = xs[i];
            if (c == 8) s8S[wid][j] = v;
            else ((float*)&seq2S[wid][j][c >> 1])[c & 1] = v;
        }
    }
    __syncthreads();

    // -0.5 * kernel-row norms (cooperative, conflict-free reads).
    for (int idx = t; idx < KM * N_FILT; idx += 256) {
        int i = idx >> 5, ff = idx & 31;
        float a = 0.f;
#pragma unroll
        for (int c = 0; c < SEQ_C; ++c) {
            float v = kTS[(i * SEQ_C + c) * KPAD + ff];
            a = fmaf(v, v, a);
        }
        knS[idx] = -0.5f * a;
    }
    // -0.5 * sequence-column norms (per warp).
    if (f < SEQ_LEN) {
        float a = 0.f;
#pragma unroll
        for (int p = 0; p < 4; ++p) {
            float2 q = seq2S[wid][f][p];
            a = fmaf(q.x, q.x, a);
            a = fmaf(q.y, q.y, a);
        }
        float v8 = s8S[wid][f];
        a = fmaf(v8, v8, a);
        hsnS[wid][f] = -0.5f * a;
    }
    __syncthreads();

    float Dp[SEQ_LEN];

    // ---- Row 0: cumsum of C[0][j] ----
    {
        float kv[SEQ_C];
#pragma unroll
        for (int c = 0; c < SEQ_C; ++c) kv[c] = kTS[c * KPAD + f];
        ull k2[4];
#pragma unroll
        for (int p = 0; p < 4; ++p) k2[p] = pack2(kv[2 * p], kv[2 * p + 1]);
        float hkn = knS[f];

        float run = 0.f;
#pragma unroll
        for (int j = 0; j < SEQ_LEN; ++j) {
            ull acc = pack2(hkn, hsnS[wid][j]);
#pragma unroll
            for (int p = 0; p < 4; ++p)
                fma2(acc, k2[p], *reinterpret_cast<const ull*>(&seq2S[wid][j][p]));
            float lo, hi; unpack2(acc, lo, hi);
            float tt = fmaf(kv[8], s8S[wid][j], lo + hi);
            run = fmaf(-2.f, tt, run);
            Dp[j] = run;
        }
    }

    const float INF = __int_as_float(0x7f800000);

    // ---- Rows 1..15 in 3 sweeps of 5 ----
    for (int sw = 0; sw < 3; ++sw) {
        const int i0 = 1 + sw * 5;
        ull  kr2[5][4];
        float kr8[5], hkn[5], left[5];
#pragma unroll
        for (int r = 0; r < 5; ++r) {
#pragma unroll
            for (int p = 0; p < 4; ++p) {
                float a = kTS[((i0 + r) * SEQ_C + 2 * p) * KPAD + f];
                float b = kTS[((i0 + r) * SEQ_C + 2 * p + 1) * KPAD + f];
                kr2[r][p] = pack2(a, b);
            }
            kr8[r] = kTS[((i0 + r) * SEQ_C + 8) * KPAD + f];
            hkn[r] = knS[(i0 + r) * N_FILT + f];
            left[r] = INF;
        }
        float diagc = INF;
#pragma unroll
        for (int j = 0; j < SEQ_LEN; ++j) {
            ull sv[4];
#pragma unroll
            for (int p = 0; p < 4; ++p)
                sv[p] = *reinterpret_cast<const ull*>(&seq2S[wid][j][p]);
            const float s8  = s8S[wid][j];
            const float hsn = hsnS[wid][j];

            float up = Dp[j];
            float oldup = up;
            float diag = diagc;
#pragma unroll
            for (int r = 0; r < 5; ++r) {
                ull acc = pack2(hkn[r], hsn);
                fma2(acc, kr2[r][0], sv[0]);
                fma2(acc, kr2[r][1], sv[1]);
                fma2(acc, kr2[r][2], sv[2]);
                fma2(acc, kr2[r][3], sv[3]);
                float lo, hi; unpack2(acc, lo, hi);
                float tt = fmaf(kr8[r], s8, lo + hi);        // dot - (kn+sn)/2
                float best = fminf(left[r], fminf(up, diag));
                float d = fmaf(-2.f, tt, best);              // C + best
                diag = left[r];
                left[r] = d;
                up = d;
            }
            Dp[j] = up;
            diagc = oldup;
        }
    }

    g_feats[s * N_FILT + f] = Dp[SEQ_LEN - 1];
}

// ---------------------------------------------------------------------------
// MLP: 256 threads, 8 sequences/block. Thread = (hidden unit hu = t&127,
// half = t>>7). Layer1: each half does 4 seqs. Layer2: halves split the
// 128-deep reduction (64 each), partials combined via smem. Activations
// stored transposed [h][seq] -> broadcast LDS.128. 8 FMA per W2 load.
// ---------------------------------------------------------------------------
__global__ __launch_bounds__(256) void mlp_kernel(
    const float* __restrict__ W1, const float* __restrict__ b1,
    const float* __restrict__ W2, const float* __restrict__ b2,
    const float* __restrict__ Wl, const float* __restrict__ bl,
    float* __restrict__ out) {
    __shared__ float fSt[N_FILT * 8];    // [filter][seq]
    __shared__ float t1S[HID * 8];       // [h][seq]
    __shared__ float t2P[HID * 8];       // partials
    __shared__ float t2S[HID * 8];       // [h][seq]

    const int t    = threadIdx.x;
    const int hu   = t & 127;
    const int half = t >> 7;
    const int s0   = blockIdx.x * SEQS_PER_MLP_BLK;

    // Stage features transposed: [filter][seq]
    {
        int sq = t >> 5, ff = t & 31;
        fSt[ff * 8 + sq] = g_feats[(s0 + sq) * N_FILT + ff];
    }
    __syncthreads();

    // ---- Layer 1 (32 -> 128): half h does seqs half*4..half*4+3 ----
    {
        float b = b1[hu];
        float a0 = b, a1 = b, a2 = b, a3 = b;
#pragma unroll
        for (int ff = 0; ff < N_FILT; ++ff) {
            float w = W1[ff * HID + hu];
            float4 v = *reinterpret_cast<const float4*>(&fSt[ff * 8 + half * 4]);
            a0 = fmaf(v.x, w, a0);
            a1 = fmaf(v.y, w, a1);
            a2 = fmaf(v.z, w, a2);
            a3 = fmaf(v.w, w, a3);
        }
        float4 r = make_float4(fmaxf(a0, 0.f), fmaxf(a1, 0.f),
                               fmaxf(a2, 0.f), fmaxf(a3, 0.f));
        *reinterpret_cast<float4*>(&t1S[hu * 8 + half * 4]) = r;
    }
    __syncthreads();

    // ---- Layer 2 (128 -> 128): half h reduces h in [half*64, half*64+64) ----
    float c0 = 0.f, c1 = 0.f, c2 = 0.f, c3 = 0.f;
    float c4 = 0.f, c5 = 0.f, c6 = 0.f, c7 = 0.f;
#pragma unroll 8
    for (int h = 0; h < 64; ++h) {
        int hh = half * 64 + h;
        float w = W2[hh * HID + hu];
        float4 va = *reinterpret_cast<const float4*>(&t1S[hh * 8]);
        float4 vb = *reinterpret_cast<const float4*>(&t1S[hh * 8 + 4]);
        c0 = fmaf(va.x, w, c0);
        c1 = fmaf(va.y, w, c1);
        c2 = fmaf(va.z, w, c2);
        c3 = fmaf(va.w, w, c3);
        c4 = fmaf(vb.x, w, c4);
        c5 = fmaf(vb.y, w, c5);
        c6 = fmaf(vb.z, w, c6);
        c7 = fmaf(vb.w, w, c7);
    }
    if (half == 0) {
        *reinterpret_cast<float4*>(&t2P[hu * 8])     = make_float4(c0, c1, c2, c3);
        *reinterpret_cast<float4*>(&t2P[hu * 8 + 4]) = make_float4(c4, c5, c6, c7);
    }
    __syncthreads();
    if (half == 1) {
        float b = b2[hu];
        float4 pa = *reinterpret_cast<const float4*>(&t2P[hu * 8]);
        float4 pb = *reinterpret_cast<const float4*>(&t2P[hu * 8 + 4]);
        float4 ra = make_float4(fmaxf(c0 + pa.x + b, 0.f), fmaxf(c1 + pa.y + b, 0.f),
                                fmaxf(c2 + pa.z + b, 0.f), fmaxf(c3 + pa.w + b, 0.f));
        float4 rb = make_float4(fmaxf(c4 + pb.x + b, 0.f), fmaxf(c5 + pb.y + b, 0.f),
                                fmaxf(c6 + pb.z + b, 0.f), fmaxf(c7 + pb.w + b, 0.f));
        *reinterpret_cast<float4*>(&t2S[hu * 8])     = ra;
        *reinterpret_cast<float4*>(&t2S[hu * 8 + 4]) = rb;
    }
    __syncthreads();

    // ---- Logits + softmax: warp w handles sequence s0 + w ----
    const int wid  = t >> 5;
    const int lane = t & 31;
    float acc[NCLS];
#pragma unroll
    for (int c = 0; c < NCLS; ++c) acc[c] = 0.f;
#pragma unroll
    for (int hh4 = 0; hh4 < 4; ++hh4) {
        int h = lane + hh4 * 32;
        float v = t2S[h * 8 + wid];
#pragma unroll
        for (int c = 0; c < NCLS; ++c) acc[c] = fmaf(v, Wl[h * NCLS + c], acc[c]);
    }
#pragma unroll
    for (int off = 16; off > 0; off >>= 1) {
#pragma unroll
        for (int c = 0; c < NCLS; ++c)
            acc[c] += __shfl_xor_sync(0xffffffffu, acc[c], off);
    }
    if (lane == 0) {
        float mx = -__int_as_float(0x7f800000);
#pragma unroll
        for (int c = 0; c < NCLS; ++c) {
            acc[c] += bl[c];
            mx = fmaxf(mx, acc[c]);
        }
        float e[NCLS];
        float sum = 0.f;
#pragma unroll
        for (int c = 0; c < NCLS; ++c) {
            e[c] = expf(acc[c] - mx);
            sum += e[c];
        }
        float inv = 1.f / sum;
#pragma unroll
        for (int c = 0; c < NCLS; ++c)
            out[(s0 + wid) * NCLS + c] = e[c] * inv;
    }
}

extern "C" void kernel_launch(void* const* d_in, const int* in_sizes, int n_in,
                              void* d_out, int out_size) {
    const float* x       = (const float*)d_in[0];
    const float* kernels = (const float*)d_in[1];
    const float* W1      = (const float*)d_in[2];
    const float* b1      = (const float*)d_in[3];
    const float* W2      = (const float*)d_in[4];
    const float* b2      = (const float*)d_in[5];
    const float* Wl      = (const float*)d_in[6];
    const float* bl      = (const float*)d_in[7];
    float* out = (float*)d_out;

    dtw_kernel<<<N_SEQ / SEQS_PER_DTW_BLK, 256>>>(x, kernels);
    mlp_kernel<<<N_SEQ / SEQS_PER_MLP_BLK, 256>>>(W1, b1, W2, b2, Wl, bl, out);
}